// round 1
// baseline (speedup 1.0000x reference)
#include <cuda_runtime.h>
#include <math.h>

#define NN 1000
#define FF 128
#define TT 4
#define PP 10
#define DD 13
#define EE 20000
#define EAD 16
#define HH 128
#define KK 64
#define NDIM 13000        // N*D
#define IEDGE 169
#define INODE 91
#define WNS 172           // padded Wn row stride (mult of 4)
#define WCPAD 68          // padded Wc smem row stride (17 float4 groups, odd -> no bank conflicts)
#define WPPAD 132         // padded Wp smem row stride (33 float4 groups, odd)

// ---------------- scratch (device globals; no runtime allocation) ----------------
__device__ float g_m[NN*FF];
__device__ float g_base[NN*FF];
__device__ float g_agg[NN*FF];
__device__ float g_r1[NN*HH];
__device__ float g_r2[NN*HH];
__device__ float g_q1[NN*KK];
__device__ float g_q2[NN*KK];
__device__ float g_Wn[TT*FF*WNS];        // [t][f][xy(pad 172)] = W_node @ cob_node
__device__ float g_WcT[PP*IEDGE*KK];     // [p][xy][k]          = (W_edge @ cob_edge)^T
__device__ float g_h[EE*2*KK];           // per-edge [h_ij(64) | h_ji(64)]
__device__ int   g_cnt[PP];
__device__ int   g_off[PP+1];
__device__ int   g_cur[PP];
__device__ int   g_bucket[EE];

// ---------------- precompute fused change-of-basis weights ----------------
__global__ void k_pre_node(const float* __restrict__ Wnode, const float* __restrict__ cobn) {
    int idx = blockIdx.x*blockDim.x + threadIdx.x;
    if (idx < TT*FF*3) {  // zero pad columns so later float4 reads are benign
        g_Wn[(idx/3)*WNS + IEDGE + (idx%3)] = 0.f;
    }
    if (idx >= TT*FF*IEDGE) return;
    int xy  = idx % IEDGE;
    int rem = idx / IEDGE;
    int f = rem % FF, t = rem / FF;
    const float* w = Wnode + (t*FF + f)*INODE;
    const float* c = cobn + t*INODE*IEDGE + xy;
    float acc = 0.f;
    #pragma unroll 7
    for (int i = 0; i < INODE; i++) acc += w[i]*c[i*IEDGE];
    g_Wn[(t*FF + f)*WNS + xy] = acc;
}

__global__ void k_pre_edge(const float* __restrict__ Wedge, const float* __restrict__ cobe) {
    int idx = blockIdx.x*blockDim.x + threadIdx.x;
    if (idx >= PP*KK*IEDGE) return;
    int xy  = idx % IEDGE;
    int rem = idx / IEDGE;
    int k = rem % KK, p = rem / KK;
    const float* w = Wedge + (p*KK + k)*IEDGE;
    const float* c = cobe + (size_t)p*IEDGE*IEDGE + xy;
    float acc = 0.f;
    #pragma unroll 13
    for (int i = 0; i < IEDGE; i++) acc += w[i]*c[i*IEDGE];
    g_WcT[(p*IEDGE + xy)*KK + k] = acc;   // transposed store: [xy][k]
}

// ---------------- node prep: m = nf@Wmsg, base = nf + na@Wattr, zero agg ----------------
__global__ void k_node_prep(const float* __restrict__ nf, const float* __restrict__ na,
                            const float* __restrict__ Wmsg, const float* __restrict__ Wattr) {
    int n = blockIdx.x;
    int f = threadIdx.x;   // 128
    __shared__ float row[FF];
    row[f] = nf[n*FF + f];
    if (n == 0 && f < PP) { g_cnt[f] = 0; g_cur[f] = 0; }
    __syncthreads();
    float acc = 0.f;
    #pragma unroll 8
    for (int g = 0; g < FF; g++) acc += row[g] * Wmsg[g*FF + f];
    g_m[n*FF + f] = acc;
    float b = row[f];
    #pragma unroll
    for (int t = 0; t < TT; t++) b += na[n*TT + t] * Wattr[t*FF + f];
    g_base[n*FF + f] = b;
    g_agg[n*FF + f] = 0.f;
}

// ---------------- symmetric edge aggregation (+ type histogram) ----------------
__global__ void k_edge_agg(const int* __restrict__ ei, const int* __restrict__ et) {
    int idx = blockIdx.x*blockDim.x + threadIdx.x;
    if (idx >= EE*FF) return;
    int e = idx >> 7, f = idx & 127;
    int s = ei[e], d = ei[EE + e];
    atomicAdd(&g_agg[d*FF + f], g_m[s*FF + f]);
    atomicAdd(&g_agg[s*FF + f], g_m[d*FF + f]);
    if (f == 0) atomicAdd(&g_cnt[et[e]], 1);
}

__global__ void k_scan() {
    if (threadIdx.x == 0 && blockIdx.x == 0) {
        int acc = 0;
        for (int p = 0; p < PP; p++) { g_off[p] = acc; acc += g_cnt[p]; }
        g_off[PP] = acc;
    }
}

__global__ void k_bucket(const int* __restrict__ et) {
    int e = blockIdx.x*blockDim.x + threadIdx.x;
    if (e >= EE) return;
    int p = et[e];
    int pos = g_off[p] + atomicAdd(&g_cur[p], 1);
    g_bucket[pos] = e;
}

// ---------------- per-node outputs: r1,r2,q1,q2 and diagonal blocks ----------------
__global__ void k_node_out(const float* __restrict__ Wem, const float* __restrict__ Wproj,
                           const int* __restrict__ ntype, float* __restrict__ M) {
    int n   = blockIdx.x;
    int tid = threadIdx.x;   // 160
    __shared__ float nh[FF];
    if (tid < FF) nh[tid] = g_base[n*FF + tid] + g_agg[n*FF + tid] * 0.05f;
    __syncthreads();
    int t = ntype[n];
    const int NTASK = 96 + 43;   // 32 r1 + 32 r2 + 16 q1 + 16 q2 + 43 nb (float4 tasks)
    for (int o = tid; o < NTASK; o += blockDim.x) {
        const float4* w4; int stride4, kind, c0;
        if (o < 32)      { c0 = o*4;        w4 = (const float4*)(Wem + c0);               stride4 = HH/4;  kind = 0; }
        else if (o < 64) { c0 = (o-32)*4;   w4 = (const float4*)(Wem + FF*HH + c0);       stride4 = HH/4;  kind = 1; }
        else if (o < 80) { c0 = (o-64)*4;   w4 = (const float4*)(Wproj + FF*KK + c0);     stride4 = KK/4;  kind = 2; }
        else if (o < 96) { c0 = (o-80)*4;   w4 = (const float4*)(Wproj + 2*FF*KK + c0);   stride4 = KK/4;  kind = 3; }
        else             { c0 = (o-96)*4;   w4 = (const float4*)(g_Wn + t*FF*WNS + c0);   stride4 = WNS/4; kind = 4; }
        float4 acc = make_float4(0.f, 0.f, 0.f, 0.f);
        #pragma unroll 4
        for (int g = 0; g < FF; g++) {
            float4 w = w4[g*stride4];
            float h = nh[g];
            acc.x += h*w.x; acc.y += h*w.y; acc.z += h*w.z; acc.w += h*w.w;
        }
        if (kind == 0)      *(float4*)&g_r1[n*HH + c0] = acc;
        else if (kind == 1) *(float4*)&g_r2[n*HH + c0] = acc;
        else if (kind == 2) *(float4*)&g_q1[n*KK + c0] = acc;
        else if (kind == 3) *(float4*)&g_q2[n*KK + c0] = acc;
        else {
            float v[4] = {acc.x, acc.y, acc.z, acc.w};
            #pragma unroll
            for (int j = 0; j < 4; j++) {
                int xy = c0 + j;
                if (xy < IEDGE) {
                    int x = xy/DD, y = xy - (xy/DD)*DD;
                    M[(n*DD + x)*NDIM + n*DD + y] = v[j];
                }
            }
        }
    }
}

// ---------------- per-edge: edge_msg -> u -> h_ij/h_ji ----------------
__global__ void k_edge_msg(const float* __restrict__ ef, const float* __restrict__ ea,
                           const float* __restrict__ Wem, const float* __restrict__ Wproj,
                           const int* __restrict__ ei) {
    __shared__ float wp[KK*WPPAD];   // [c(64)][g(128) pad 132] = W_proj rows 0..127 transposed
    __shared__ float msg[HH];
    __shared__ float eatt[2*EAD];
    int tid = threadIdx.x;   // 128
    float emreg[32];         // column tid of W_em rows 256..287 (edge_feats/attrs part)
    #pragma unroll
    for (int j = 0; j < 32; j++) emreg[j] = Wem[(2*FF + j)*HH + tid];
    for (int i = tid; i < FF*KK; i += blockDim.x) {
        int r = i >> 6, c = i & 63;       // coalesced read of Wproj, transpose into smem
        wp[c*WPPAD + r] = Wproj[i];
    }
    __syncthreads();
    for (int e = blockIdx.x; e < EE; e += gridDim.x) {
        int s = ei[e], d = ei[EE + e];
        if (tid < 2*EAD) eatt[tid] = (tid < EAD) ? ef[e*EAD + tid] : ea[e*EAD + (tid - EAD)];
        __syncthreads();
        float fe = 0.f;
        #pragma unroll
        for (int j = 0; j < 32; j++) fe += eatt[j]*emreg[j];
        msg[tid] = tanhf(g_r1[s*HH + tid] + g_r2[d*HH + tid] + fe);
        __syncthreads();
        if (tid < KK) {
            const float4* wr = (const float4*)&wp[tid*WPPAD];
            const float4* mg = (const float4*)msg;
            float u = 0.f;
            #pragma unroll 8
            for (int g = 0; g < HH/4; g++) {
                float4 a = wr[g], b = mg[g];
                u += a.x*b.x + a.y*b.y + a.z*b.z + a.w*b.w;
            }
            g_h[e*2*KK + tid]      = u + g_q1[s*KK + tid] + g_q2[d*KK + tid];
            g_h[e*2*KK + KK + tid] = u + g_q1[d*KK + tid] + g_q2[s*KK + tid];
        }
        __syncthreads();
    }
}

// ---------------- per-edge 13x13 blocks + symmetric scatter ----------------
__global__ void k_edge_blocks(const int* __restrict__ ei, float* __restrict__ M) {
    int p   = blockIdx.y;
    int tid = threadIdx.x;   // 192
    __shared__ float wc[IEDGE*WCPAD];   // [xy][k pad 68]
    __shared__ float hsm[4*2*KK];       // 4 edges x [h_ij|h_ji]
    __shared__ int   einfo[8];
    const float* srcw = g_WcT + p*IEDGE*KK;
    for (int i = tid; i < IEDGE*(KK/4); i += blockDim.x) {
        int xy = i >> 4, kk = i & 15;
        ((float4*)(wc + xy*WCPAD))[kk] = ((const float4*)(srcw + xy*KK))[kk];
    }
    int beg = g_off[p], end = g_off[p+1];
    int cnt = end - beg;
    int per = (cnt + gridDim.x - 1) / gridDim.x;
    int lo  = beg + blockIdx.x * per;
    int hi  = min(lo + per, end);
    __syncthreads();
    if (lo >= hi) return;   // uniform per block
    int x = 0, y = 0, xyt = 0;
    if (tid < IEDGE) { x = tid/DD; y = tid - x*DD; xyt = y*DD + x; }
    for (int base = lo; base < hi; base += 4) {
        int ne = min(4, hi - base);
        for (int i = tid; i < 4*2*KK; i += blockDim.x) {
            int el = i >> 7, off = i & 127;
            float v = 0.f;
            if (el < ne) v = g_h[(size_t)g_bucket[base + el]*2*KK + off];
            hsm[i] = v;
        }
        if (tid < 8) {
            int el = tid >> 1;
            int e = g_bucket[base + min(el, ne - 1)];
            einfo[tid] = ei[(tid & 1)*EE + e];   // [src,dst] per edge
        }
        __syncthreads();
        if (tid < IEDGE) {
            const float4* wf = (const float4*)(wc + tid*WCPAD);
            const float4* wt = (const float4*)(wc + xyt*WCPAD);
            const float4* h4 = (const float4*)hsm;
            float a[4] = {0.f,0.f,0.f,0.f}, b[4] = {0.f,0.f,0.f,0.f};
            #pragma unroll
            for (int kk = 0; kk < KK/4; kk++) {
                float4 f = wf[kk], t = wt[kk];
                #pragma unroll
                for (int el = 0; el < 4; el++) {
                    float4 hf = h4[el*32 + kk];        // h_ij
                    float4 hb = h4[el*32 + 16 + kk];   // h_ji
                    a[el] += hf.x*f.x + hf.y*f.y + hf.z*f.z + hf.w*f.w;
                    b[el] += hb.x*t.x + hb.y*t.y + hb.z*t.z + hb.w*t.w;
                }
            }
            #pragma unroll
            for (int el = 0; el < 4; el++) {
                if (el < ne) {
                    float v = 0.5f*(a[el] + b[el]);
                    int s = einfo[2*el], d = einfo[2*el + 1];
                    atomicAdd(&M[(s*DD + x)*NDIM + d*DD + y], v);
                    atomicAdd(&M[(d*DD + y)*NDIM + s*DD + x], v);
                }
            }
        }
        __syncthreads();
    }
}

// ---------------- launcher ----------------
extern "C" void kernel_launch(void* const* d_in, const int* in_sizes, int n_in,
                              void* d_out, int out_size) {
    const float* nf    = (const float*)d_in[0];
    const float* na    = (const float*)d_in[1];
    const float* ef    = (const float*)d_in[2];
    const float* ea    = (const float*)d_in[3];
    const int*   ei    = (const int*)d_in[4];
    const int*   ntype = (const int*)d_in[5];
    const int*   etype = (const int*)d_in[6];
    const float* Wmsg  = (const float*)d_in[7];
    const float* Wattr = (const float*)d_in[8];
    const float* Wem   = (const float*)d_in[9];
    const float* Wproj = (const float*)d_in[10];
    const float* Wnode = (const float*)d_in[11];
    const float* Wedge = (const float*)d_in[12];
    const float* cobn  = (const float*)d_in[13];
    const float* cobe  = (const float*)d_in[14];
    float* M = (float*)d_out;

    cudaMemsetAsync(M, 0, (size_t)out_size * sizeof(float));
    k_pre_node<<<(TT*FF*IEDGE + 255)/256, 256>>>(Wnode, cobn);
    k_pre_edge<<<(PP*KK*IEDGE + 255)/256, 256>>>(Wedge, cobe);
    k_node_prep<<<NN, FF>>>(nf, na, Wmsg, Wattr);
    k_edge_agg<<<(EE*FF + 255)/256, 256>>>(ei, etype);
    k_scan<<<1, 32>>>();
    k_bucket<<<(EE + 255)/256, 256>>>(etype);
    k_node_out<<<NN, 160>>>(Wem, Wproj, ntype, M);
    k_edge_msg<<<512, 128>>>(ef, ea, Wem, Wproj, ei);
    k_edge_blocks<<<dim3(64, PP), 192>>>(ei, M);
}